// round 4
// baseline (speedup 1.0000x reference)
#include <cuda_runtime.h>

// LSTM: B=4096, T=512, I=10, H=32, O=1. Gate order i,f,g,o.
// R4: R2 structure (all 4 gates' recurrent weights in registers as f32x2
// pairs; even/odd-j halves accumulate in the u64 halves) but NB=2 batches
// per warp -> 2048 independent single-warp blocks to hide LDS/MUFU latency.
// No inter-warp coupling of the recurrence.

#define B_TOT 4096
#define T_LEN 512
#define I_DIM 10
#define H_DIM 32
#define NB 2
#define NPX 5    // x pairs (10/2)

typedef unsigned long long u64;

__device__ __forceinline__ u64 fma2(u64 a, u64 b, u64 c) {
    u64 d;
    asm("fma.rn.f32x2 %0, %1, %2, %3;" : "=l"(d) : "l"(a), "l"(b), "l"(c));
    return d;
}
__device__ __forceinline__ u64 pack2(float lo, float hi) {
    u64 d;
    asm("mov.b64 %0, {%1, %2};" : "=l"(d) : "f"(lo), "f"(hi));
    return d;
}
__device__ __forceinline__ void unpack2(u64 v, float& lo, float& hi) {
    asm("mov.b64 {%0, %1}, %2;" : "=f"(lo), "=f"(hi) : "l"(v));
}
__device__ __forceinline__ float ex2f(float x) {
    float y; asm("ex2.approx.f32 %0, %1;" : "=f"(y) : "f"(x)); return y;
}
__device__ __forceinline__ float rcpf(float x) {
    float y; asm("rcp.approx.f32 %0, %1;" : "=f"(y) : "f"(x)); return y;
}
__device__ __forceinline__ float sigf(float x) {
    return rcpf(1.0f + ex2f(-1.4426950408889634f * x));
}
__device__ __forceinline__ float tanh_f(float x) {
    return fmaf(2.0f, rcpf(1.0f + ex2f(-2.8853900817779268f * x)), -1.0f);
}

__global__ __launch_bounds__(32, 10) void lstm_warp2_kernel(
    const float* __restrict__ x,    // [B, T, I]
    const float* __restrict__ Wih,  // [4H, I]
    const float* __restrict__ Whh,  // [4H, H]
    const float* __restrict__ bih,  // [4H]
    const float* __restrict__ bhh,  // [4H]
    const float* __restrict__ Wd,   // [1, H]
    const float* __restrict__ bd,   // [1]
    float* __restrict__ out)        // [B, 1]
{
    // x-weights in smem: per (pair p, lane): (w_i, w_f) and (w_g, w_o) 16B rows.
    __shared__ ulonglong2 sWx_if[NPX][32];
    __shared__ ulonglong2 sWx_go[NPX][32];
    __shared__ __align__(16) float sH[NB][H_DIM];
    __shared__ __align__(16) float sX[NB][12];

    const int lane = threadIdx.x;
    const int b0 = blockIdx.x * NB;

    // ---- Prologue: recurrent weights into registers (paired over j) ----
    u64 whi[16], whf[16], whg[16], who[16];
#pragma unroll
    for (int p = 0; p < 16; p++) {
        whi[p] = *(const u64*)&Whh[(0 * 32 + lane) * H_DIM + 2 * p];
        whf[p] = *(const u64*)&Whh[(1 * 32 + lane) * H_DIM + 2 * p];
        whg[p] = *(const u64*)&Whh[(2 * 32 + lane) * H_DIM + 2 * p];
        who[p] = *(const u64*)&Whh[(3 * 32 + lane) * H_DIM + 2 * p];
    }
    // x-weights into smem.
#pragma unroll
    for (int p = 0; p < NPX; p++) {
        ulonglong2 v;
        v.x = pack2(Wih[(0 * 32 + lane) * I_DIM + 2 * p], Wih[(0 * 32 + lane) * I_DIM + 2 * p + 1]);
        v.y = pack2(Wih[(1 * 32 + lane) * I_DIM + 2 * p], Wih[(1 * 32 + lane) * I_DIM + 2 * p + 1]);
        sWx_if[p][lane] = v;
        v.x = pack2(Wih[(2 * 32 + lane) * I_DIM + 2 * p], Wih[(2 * 32 + lane) * I_DIM + 2 * p + 1]);
        v.y = pack2(Wih[(3 * 32 + lane) * I_DIM + 2 * p], Wih[(3 * 32 + lane) * I_DIM + 2 * p + 1]);
        sWx_go[p][lane] = v;
    }
    const float bias_i = bih[0 * 32 + lane] + bhh[0 * 32 + lane];
    const float bias_f = bih[1 * 32 + lane] + bhh[1 * 32 + lane];
    const float bias_g = bih[2 * 32 + lane] + bhh[2 * 32 + lane];
    const float bias_o = bih[3 * 32 + lane] + bhh[3 * 32 + lane];
    __syncwarp();

    float h[NB], c[NB], xv[NB];
#pragma unroll
    for (int k = 0; k < NB; k++) { h[k] = 0.0f; c[k] = 0.0f; xv[k] = 0.0f; }

    const float* xp0 = x + ((b0 + 0) * T_LEN) * I_DIM + lane;
    const float* xp1 = x + ((b0 + 1) * T_LEN) * I_DIM + lane;
    if (lane < I_DIM) { xv[0] = *xp0; xv[1] = *xp1; }

    for (int t = 0; t < T_LEN; t++) {
        // Publish compact h and x.
        sH[0][lane] = h[0];
        sH[1][lane] = h[1];
        if (lane < I_DIM) {
            sX[0][lane] = xv[0];
            sX[1][lane] = xv[1];
        }
        __syncwarp();

        // Prefetch next timestep's x (overlaps gate compute below).
        if (t + 1 < T_LEN) {
            xp0 += I_DIM; xp1 += I_DIM;
            if (lane < I_DIM) { xv[0] = *xp0; xv[1] = *xp1; }
        }

        // Accumulators: lo half = even-j sum, hi half = odd-j sum.
        u64 ai[NB], af[NB], ag[NB], ao[NB];
#pragma unroll
        for (int k = 0; k < NB; k++) { ai[k] = 0; af[k] = 0; ag[k] = 0; ao[k] = 0; }

        // Recurrent part: register weights x uniform-broadcast h pairs.
#pragma unroll
        for (int k = 0; k < NB; k++) {
#pragma unroll
            for (int q = 0; q < 8; q++) {
                const ulonglong2 hp = *(const ulonglong2*)&sH[k][4 * q];
                ai[k] = fma2(whi[2 * q], hp.x, ai[k]);
                af[k] = fma2(whf[2 * q], hp.x, af[k]);
                ag[k] = fma2(whg[2 * q], hp.x, ag[k]);
                ao[k] = fma2(who[2 * q], hp.x, ao[k]);
                ai[k] = fma2(whi[2 * q + 1], hp.y, ai[k]);
                af[k] = fma2(whf[2 * q + 1], hp.y, af[k]);
                ag[k] = fma2(whg[2 * q + 1], hp.y, ag[k]);
                ao[k] = fma2(who[2 * q + 1], hp.y, ao[k]);
            }
        }
        // Input part: p-outer so only 4 weight u64s live at a time.
#pragma unroll
        for (int p = 0; p < NPX; p++) {
            const ulonglong2 wif = sWx_if[p][lane];
            const ulonglong2 wgo = sWx_go[p][lane];
#pragma unroll
            for (int k = 0; k < NB; k++) {
                const u64 xp = *(const u64*)&sX[k][2 * p];
                ai[k] = fma2(wif.x, xp, ai[k]);
                af[k] = fma2(wif.y, xp, af[k]);
                ag[k] = fma2(wgo.x, xp, ag[k]);
                ao[k] = fma2(wgo.y, xp, ao[k]);
            }
        }

        // Activations + state update.
#pragma unroll
        for (int k = 0; k < NB; k++) {
            float lo, hi;
            unpack2(ai[k], lo, hi); const float gi = sigf(lo + hi + bias_i);
            unpack2(af[k], lo, hi); const float gf = sigf(lo + hi + bias_f);
            unpack2(ag[k], lo, hi); const float gg = tanh_f(lo + hi + bias_g);
            unpack2(ao[k], lo, hi); const float go = sigf(lo + hi + bias_o);
            c[k] = fmaf(gf, c[k], gi * gg);
            h[k] = go * tanh_f(c[k]);
        }
        __syncwarp();
    }

    // Final dense: out[b] = sum_l h[b][l] * Wd[l] + bd
    const float wd = Wd[lane];
    const float bdv = bd[0];
#pragma unroll
    for (int k = 0; k < NB; k++) {
        float p = h[k] * wd;
#pragma unroll
        for (int off = 16; off; off >>= 1)
            p += __shfl_xor_sync(0xffffffffu, p, off);
        if (lane == 0) out[b0 + k] = p + bdv;
    }
}

extern "C" void kernel_launch(void* const* d_in, const int* in_sizes, int n_in,
                              void* d_out, int out_size) {
    const float* x   = (const float*)d_in[0];
    const float* Wih = (const float*)d_in[1];
    const float* Whh = (const float*)d_in[2];
    const float* bih = (const float*)d_in[3];
    const float* bhh = (const float*)d_in[4];
    const float* Wd  = (const float*)d_in[5];
    const float* bd  = (const float*)d_in[6];
    (void)in_sizes; (void)n_in; (void)out_size;

    lstm_warp2_kernel<<<B_TOT / NB, 32>>>(x, Wih, Whh, bih, bhh, Wd, bd,
                                          (float*)d_out);
}